// round 16
// baseline (speedup 1.0000x reference)
#include <cuda_runtime.h>
#include <cuda_fp16.h>
#include <cstdint>

#define C      64
#define KW     21
#define T_IN   16384
#define TC     (T_IN - KW + 1)   // 16364
#define B      32
#define MT     128
#define NTILES 128
#define TROWS  16512             // padded transposed-x rows (129*128)
#define TSPLIT 32

// smem (bytes): xs[21312] wpair0[36864] wpair1[36864]; epilogue ep+red alias
#define XS_B     21312
#define WB_OFF   21312
#define WSLOT    18432
#define WPAIR    36864
#define RED_OFF  69632
#define SMEM_TOTAL 95744

// ---------------- device scratch (no allocations allowed) -------------------
__device__ uint4    g_wh[21 * 1024];               // W images [k][n=128][ci=64] fp16
__device__ uint4    g_xh[(size_t)B * TROWS * 8];   // X transposed [b][t][ci] fp16
__device__ __half   g_y2[(size_t)B * 16384 * 64];  // avg-branch y [b][t][c] fp16
__device__ float    g_sum[128];
__device__ float    g_sumsq[128];
__device__ unsigned g_mm[B * 64 * 4];              // enc(max), enc(-min) per bin0/1
__device__ float    g_favg[B * 192];               // avg-branch sums (atomic acc)
__device__ unsigned g_cnt[B];                      // spp completion counters

// ---------------- helpers ----------------------------------------------------
__device__ __forceinline__ uint32_t smem_u32(const void* p) {
    uint32_t a;
    asm("{ .reg .u64 t; cvta.to.shared.u64 t, %1; cvt.u32.u64 %0, t; }" : "=r"(a) : "l"(p));
    return a;
}
__device__ __forceinline__ void cpa16(uint32_t dst, const void* src) {
    asm volatile("cp.async.cg.shared.global [%0], [%1], 16;" :: "r"(dst), "l"(src));
}
#define CP_COMMIT() asm volatile("cp.async.commit_group;" ::: "memory")
#define CP_WAIT0()  asm volatile("cp.async.wait_group 0;" ::: "memory")

__device__ __forceinline__ void ldsm4(uint32_t* r, uint32_t a) {
    asm volatile("ldmatrix.sync.aligned.m8n8.x4.shared.b16 {%0,%1,%2,%3}, [%4];"
                 : "=r"(r[0]), "=r"(r[1]), "=r"(r[2]), "=r"(r[3]) : "r"(a));
}
__device__ __forceinline__ void mma16816(float* d, const uint32_t* a, const uint32_t* b2) {
    asm volatile(
        "mma.sync.aligned.m16n8k16.row.col.f32.f16.f16.f32 "
        "{%0,%1,%2,%3},{%4,%5,%6,%7},{%8,%9},{%0,%1,%2,%3};"
        : "+f"(d[0]), "+f"(d[1]), "+f"(d[2]), "+f"(d[3])
        : "r"(a[0]), "r"(a[1]), "r"(a[2]), "r"(a[3]), "r"(b2[0]), "r"(b2[1]));
}
__device__ __forceinline__ uint32_t pack_h(float a, float b) {
    __half ha = __float2half_rn(a), hb = __float2half_rn(b);
    return (uint32_t)__half_as_ushort(ha) | ((uint32_t)__half_as_ushort(hb) << 16);
}
__device__ __forceinline__ uint32_t fenc(float f) {
    uint32_t u = __float_as_uint(f);
    return (u & 0x80000000u) ? ~u : (u | 0x80000000u);
}
__device__ __forceinline__ float fdec(uint32_t u) {
    return __uint_as_float((u & 0x80000000u) ? (u ^ 0x80000000u) : ~u);
}
// inline BN stats -> (scale, shift) for channel i (0..127)
__device__ __forceinline__ float2 bn_coef(int i, float gamma, float beta) {
    float n = (float)B * (float)TC;
    float mean = g_sum[i] / n;
    float var  = g_sumsq[i] / n - mean * mean;
    float sc = rsqrtf(var + 1e-5f) * gamma;
    return make_float2(sc, beta - mean * sc);
}

// ---------------------------------------------------------------------------
// Merged prep: grid (130, 32).
//   x < 129 : transpose x -> g_xh [b][t][ci] fp16
//   x == 129: y < 21 -> W image for k=y; y == 21 -> init accumulators
__global__ void __launch_bounds__(256) k_prep(const float* __restrict__ x,
                                              const float* __restrict__ w1,
                                              const float* __restrict__ w2) {
    if (blockIdx.x == 129) {
        int k = blockIdx.y;
        if (k < KW) {
            uint32_t* dh = (uint32_t*)g_wh;
            for (int idx = threadIdx.x; idx < 128 * 32; idx += 256) {
                int n = idx >> 5, p = idx & 31, ci = 2 * p;
                const float* src = (n < 64) ? (w1 + ((size_t)n * C + ci) * KW + k)
                                            : (w2 + ((size_t)(n - 64) * C + ci) * KW + k);
                dh[(k * 128 + n) * 32 + p] = pack_h(src[0], src[KW]);
            }
        } else if (k == KW) {
            int i = threadIdx.x;
            if (i < 128) { g_sum[i] = 0.f; g_sumsq[i] = 0.f; }
            if (i < B) g_cnt[i] = 0u;
            const uint32_t NEGINF = 0x007FFFFFu;   // fenc(-inf)
            for (int j = i; j < B * 64 * 4; j += 256) g_mm[j] = NEGINF;
            for (int j = i; j < B * 192; j += 256) g_favg[j] = 0.f;
        }
        return;
    }
    __shared__ float smx[64][129];
    int b = blockIdx.y, t0 = blockIdx.x * 128;
    for (int idx = threadIdx.x; idx < 64 * 128; idx += 256) {
        int ci = idx >> 7, tt = idx & 127;
        int t = t0 + tt;
        smx[ci][tt] = (t < T_IN) ? x[((size_t)b * C + ci) * T_IN + t] : 0.f;
    }
    __syncthreads();
    uint32_t* dh = (uint32_t*)g_xh;
    for (int idx = threadIdx.x; idx < 128 * 32; idx += 256) {
        int tt = idx >> 5, p = idx & 31;
        size_t gi = ((size_t)b * TROWS + t0 + tt) * 32 + p;
        dh[gi] = pack_h(smx[2 * p][tt], smx[2 * p + 1][tt]);
    }
}

// ---------------------------------------------------------------------------
__device__ __forceinline__ void stage_w(uint32_t dst, int k, int tid) {
    const uint4* sh = g_wh + (size_t)k * 1024;
    for (int i = tid; i < 1024; i += 256) {
        int r = i >> 3, c2 = i & 7;
        cpa16(dst + r * 144 + c2 * 16, sh + i);
    }
}

// Main mma.sync conv: block (tile, b), 256 threads = 8 warps (2m x 4n),
// warp tile 64x32, D[t=128][n=128] in registers. 2 k per mainloop iteration.
// Epilogue: BN sums + fused exact max-pool bins (n<64), fp16 store (n>=64).
__global__ void __launch_bounds__(256, 2) k_conv(const int* __restrict__ orig_len) {
    extern __shared__ __align__(1024) char sm[];
    const int tile = blockIdx.x, b = blockIdx.y;
    const int t0 = tile * MT;
    const int tid = threadIdx.x;
    const int wid = tid >> 5, lane = tid & 31;
    const int wm = wid & 1, wn = wid >> 1;

    const uint32_t sm_u = smem_u32(sm);
    const uint32_t xs_h = sm_u;
    const uint32_t wb_u = sm_u + WB_OFF;

    // stage X tile (148 rows) + W[0], W[1] into pair-buffer 0
    {
        const uint4* sxh = g_xh + ((size_t)b * TROWS + t0) * 8;
        for (int i = tid; i < 1184; i += 256) {
            int r = i >> 3, c2 = i & 7;
            cpa16(xs_h + r * 144 + c2 * 16, sxh + i);
        }
        stage_w(wb_u, 0, tid);
        stage_w(wb_u + WSLOT, 1, tid);
        CP_COMMIT();
    }
    const int L = orig_len[b] - (KW - 1);
    const int strd = L >> 1, kern = (L + 1) >> 1;

    // per-warp ldmatrix base addresses
    uint32_t cA[4];
#pragma unroll
    for (int i = 0; i < 4; i++)
        cA[i] = (uint32_t)((wm * 64 + i * 16 + (lane & 15)) * 144 + ((lane >> 4) * 16));
    uint32_t cB[2];
#pragma unroll
    for (int p = 0; p < 2; p++)
        cB[p] = (uint32_t)((wn * 32 + p * 16 + ((lane >> 4) << 3) + (lane & 7)) * 144 +
                           (((lane >> 3) & 1) * 16));

    float acc[4][4][4];
#pragma unroll
    for (int i = 0; i < 4; i++)
#pragma unroll
        for (int j = 0; j < 4; j++)
#pragma unroll
            for (int e = 0; e < 4; e++) acc[i][j][e] = 0.f;

    CP_WAIT0();
    __syncthreads();

#pragma unroll 1
    for (int kk = 0; kk < KW; kk += 2) {
        const int buf = (kk >> 1) & 1;
        const uint32_t base = wb_u + buf * WPAIR;
        if (kk + 2 < KW) {
            const uint32_t nb = wb_u + (buf ^ 1) * WPAIR;
            stage_w(nb, kk + 2, tid);
            if (kk + 3 < KW) stage_w(nb + WSLOT, kk + 3, tid);
            CP_COMMIT();
        }
#pragma unroll 1
        for (int kq = 0; kq < 2; kq++) {
            const int k = kk + kq;
            if (k >= KW) break;
            const uint32_t axh = xs_h + k * 144;
            const uint32_t bwh = base + kq * WSLOT;
#pragma unroll
            for (int ks = 0; ks < 4; ks++) {
                uint32_t ah[4][4], bh[2][4];
#pragma unroll
                for (int i = 0; i < 4; i++) ldsm4(ah[i], axh + cA[i] + ks * 32);
#pragma unroll
                for (int p = 0; p < 2; p++) ldsm4(bh[p], bwh + cB[p] + ks * 32);
#pragma unroll
                for (int i = 0; i < 4; i++)
#pragma unroll
                    for (int j = 0; j < 4; j++)
                        mma16816(acc[i][j], ah[i], &bh[j >> 1][(j & 1) * 2]);
            }
        }
        CP_WAIT0();
        __syncthreads();
    }

    // Epilogue: acc -> smem [t][n] (stride 136 floats; aliases X+W regions)
    float* ep = (float*)sm;
#pragma unroll
    for (int i = 0; i < 4; i++) {
        int tl = wm * 64 + i * 16 + (lane >> 2);
#pragma unroll
        for (int j = 0; j < 4; j++) {
            int nn = wn * 32 + j * 8 + (lane & 3) * 2;
            *(float2*)&ep[tl * 136 + nn]       = make_float2(acc[i][j][0], acc[i][j][1]);
            *(float2*)&ep[(tl + 8) * 136 + nn] = make_float2(acc[i][j][2], acc[i][j][3]);
        }
    }
    __syncthreads();
    // BN + max-pool scan: 2-way t-split, all 8 warps
    {
        float* red = (float*)(sm + RED_OFF);
        const int n = tid & 127, half = tid >> 7;
        float s = 0.f, q = 0.f;
        float m0 = -INFINITY, m1 = -INFINITY, n0 = -INFINITY, n1 = -INFINITY;
        const int tbeg = half * 64, tend = tbeg + 64;
        for (int t = tbeg; t < tend; t++) {
            int tt = t0 + t;
            if (tt < TC) {
                float v = ep[t * 136 + n];
                s += v; q = fmaf(v, v, q);
                if (n < 64) {
                    if (tt < kern)            { m0 = fmaxf(m0, v); n0 = fmaxf(n0, -v); }
                    if (tt >= strd && tt < L) { m1 = fmaxf(m1, v); n1 = fmaxf(n1, -v); }
                }
            }
        }
        red[tid]        = s;  red[256 + tid]  = q;
        red[512 + tid]  = m0; red[768 + tid]  = n0;
        red[1024 + tid] = m1; red[1280 + tid] = n1;
        __syncthreads();
        if (tid < 128) {
            atomicAdd(&g_sum[tid],   red[tid] + red[tid + 128]);
            atomicAdd(&g_sumsq[tid], red[256 + tid] + red[384 + tid]);
            if (tid < 64) {
                unsigned* mm = g_mm + (b * 64 + tid) * 4;
                atomicMax(&mm[0], fenc(fmaxf(red[512 + tid],  red[640 + tid])));
                atomicMax(&mm[1], fenc(fmaxf(red[768 + tid],  red[896 + tid])));
                atomicMax(&mm[2], fenc(fmaxf(red[1024 + tid], red[1152 + tid])));
                atomicMax(&mm[3], fenc(fmaxf(red[1280 + tid], red[1408 + tid])));
            }
        }
    }
    // store avg-branch y (n in [64,128)) as fp16 [b][t][c]
    __half* ybase = g_y2 + ((size_t)b * 16384 + t0) * 64;
    for (int i = tid; i < 2048; i += 256) {
        int t = i >> 4, p4 = i & 15;
        float4 v = *(float4*)&ep[t * 136 + 64 + p4 * 4];
        __half2 h0 = __floats2half2_rn(v.x, v.y);
        __half2 h1 = __floats2half2_rn(v.z, v.w);
        uint2 u;
        u.x = *(uint32_t*)&h0;
        u.y = *(uint32_t*)&h1;
        *(uint2*)(ybase + (size_t)t * 64 + p4 * 4) = u;
    }
}

// ---------------------------------------------------------------------------
// Avg-branch SPP partial pass over fp16 y2 [b][t][c(64)]. TSPLIT blocks per b;
// partials combined via atomicAdd into g_favg. The LAST block per b (atomic
// ticket) finalizes: feat (max branch from g_mm, avg from g_favg) -> FC -> out.
__global__ void __launch_bounds__(256) k_spp(const int* __restrict__ orig_len,
                                             const float* __restrict__ g1,
                                             const float* __restrict__ b1,
                                             const float* __restrict__ g2,
                                             const float* __restrict__ b2,
                                             const float* __restrict__ fc_w,
                                             const float* __restrict__ fc_b,
                                             float* __restrict__ out) {
    const int s = blockIdx.x, b = blockIdx.y;
    const int L = orig_len[b] - (KW - 1);
    const int strd = L >> 1, kern = (L + 1) >> 1;
    const int chunk = (L + TSPLIT - 1) / TSPLIT;
    const int tb = s * chunk;
    const int te = min(L, tb + chunk);
    const int p = threadIdx.x & 31, h = threadIdx.x >> 5;
    const int c0 = 2 * p, c1 = 2 * p + 1;
    float2 k0 = bn_coef(64 + c0, g2[c0], b2[c0]);
    float2 k1 = bn_coef(64 + c1, g2[c1], b2[c1]);
    const __half2* __restrict__ base =
        (const __half2*)g_y2 + (size_t)b * 16384 * 32 + p;

    float2 sa = make_float2(0.f, 0.f), s0 = sa, s1 = sa;
#pragma unroll 8
    for (int t = tb + h; t < te; t += 8) {
        float2 v = __half22float2(base[(size_t)t * 32]);
        v.x = fmaf(v.x, k0.x, k0.y); v.y = fmaf(v.y, k1.x, k1.y);
        v.x = (v.x > 0.f) ? v.x : 0.01f * v.x;
        v.y = (v.y > 0.f) ? v.y : 0.01f * v.y;
        sa.x += v.x; sa.y += v.y;
        if (t < kern) { s0.x += v.x; s0.y += v.y; }
        if (t >= strd) { s1.x += v.x; s1.y += v.y; }
    }
    __shared__ float2 r0[256], r1[256], r2[256];
    __shared__ unsigned s_last;
    r0[threadIdx.x] = sa; r1[threadIdx.x] = s0; r2[threadIdx.x] = s1;
    __syncthreads();
    if (h == 0) {
#pragma unroll
        for (int g = 1; g < 8; g++) {
            int o = threadIdx.x + g * 32;
            sa.x += r0[o].x; sa.y += r0[o].y;
            s0.x += r1[o].x; s0.y += r1[o].y;
            s1.x += r2[o].x; s1.y += r2[o].y;
        }
        float* pp = g_favg + b * 192;
        atomicAdd(&pp[c0], sa.x);        atomicAdd(&pp[c1], sa.y);
        atomicAdd(&pp[64 + c0], s0.x);   atomicAdd(&pp[64 + c1], s0.y);
        atomicAdd(&pp[128 + c0], s1.x);  atomicAdd(&pp[128 + c1], s1.y);
    }
    __syncthreads();
    // completion ticket: last block for this b finalizes
    if (threadIdx.x == 0) {
        __threadfence();
        s_last = atomicAdd(&g_cnt[b], 1u);
    }
    __syncthreads();
    if (s_last != TSPLIT - 1) return;
    __threadfence();

    // ---- finalize (one block per b) ----
    __shared__ float feat[384];
    const int n = threadIdx.x;
    if (n < 128) {
        if (n < 64) {
            float2 kk = bn_coef(n, g1[n], b1[n]);
            const unsigned* mm = g_mm + (b * 64 + n) * 4;
            float M0 = fdec(mm[0]), N0 = -fdec(mm[1]);
            float M1 = fdec(mm[2]), N1 = -fdec(mm[3]);
            float v0 = (kk.x >= 0.f) ? fmaf(kk.x, M0, kk.y) : fmaf(kk.x, N0, kk.y);
            float v1 = (kk.x >= 0.f) ? fmaf(kk.x, M1, kk.y) : fmaf(kk.x, N1, kk.y);
            v0 = (v0 > 0.f) ? v0 : 0.01f * v0;
            v1 = (v1 > 0.f) ? v1 : 0.01f * v1;
            feat[n] = fmaxf(v0, v1);
            feat[64 + 2 * n] = v0;
            feat[65 + 2 * n] = v1;
        } else {
            int c = n - 64;
            const float* pp = g_favg + b * 192;
            feat[192 + c] = pp[c] / (float)L;
            feat[256 + 2 * c] = pp[64 + c] / (float)kern;
            feat[257 + 2 * c] = pp[128 + c] / (float)kern;
        }
    }
    __syncthreads();
    if (n < 64) {
        int task = n >> 5, lane = n & 31;
        float acc = 0.f;
        for (int j = lane; j < 384; j += 32)
            acc = fmaf(feat[j], fc_w[task * 384 + j], acc);
#pragma unroll
        for (int off = 16; off; off >>= 1)
            acc += __shfl_down_sync(0xffffffffu, acc, off);
        if (lane == 0) out[b * 2 + task] = acc + fc_b[task];
    }
}

// ---------------------------------------------------------------------------
extern "C" void kernel_launch(void* const* d_in, const int* in_sizes, int n_in,
                              void* d_out, int out_size) {
    const float* x        = (const float*)d_in[0];
    const int*   orig_len = (const int*)  d_in[1];
    const float* w1       = (const float*)d_in[2];
    const float* g1       = (const float*)d_in[3];
    const float* b1       = (const float*)d_in[4];
    const float* w2       = (const float*)d_in[5];
    const float* g2       = (const float*)d_in[6];
    const float* b2       = (const float*)d_in[7];
    const float* fcw      = (const float*)d_in[8];
    const float* fcb      = (const float*)d_in[9];
    float* out = (float*)d_out;

    cudaFuncSetAttribute(k_conv, cudaFuncAttributeMaxDynamicSharedMemorySize,
                         SMEM_TOTAL);

    dim3 gp(130, 32);
    k_prep<<<gp, 256>>>(x, w1, w2);
    dim3 gc(NTILES, B);
    k_conv<<<gc, 256, SMEM_TOTAL>>>(orig_len);
    dim3 gs(TSPLIT, B);
    k_spp<<<gs, 256>>>(orig_len, g1, b1, g2, b2, fcw, fcb, out);
}

// round 17
// speedup vs baseline: 1.0175x; 1.0175x over previous
#include <cuda_runtime.h>
#include <cuda_fp16.h>
#include <cstdint>

#define C      64
#define KW     21
#define T_IN   16384
#define TC     (T_IN - KW + 1)   // 16364
#define B      32
#define MT     128
#define NTILES 128
#define TROWS  16512             // padded transposed-x rows (129*128)
#define TSPLIT 32

// smem (bytes): xs[21312] wpair0[36864] wpair1[36864]; epilogue ep+red alias
#define XS_B     21312
#define WB_OFF   21312
#define WSLOT    18432
#define WPAIR    36864
#define RED_OFF  69632
#define SMEM_TOTAL 95744

// ---------------- device scratch (no allocations allowed) -------------------
__device__ uint4    g_wh[21 * 1024];               // W images [k][n=128][ci=64] fp16
__device__ uint4    g_xh[(size_t)B * TROWS * 8];   // X transposed [b][t][ci] fp16
__device__ __half   g_y2[(size_t)B * 16384 * 64];  // avg-branch y [b][t][c] fp16
__device__ float    g_sum[128];
__device__ float    g_sumsq[128];
__device__ unsigned g_mm[B * 64 * 4];              // enc(max), enc(-min) per bin0/1
__device__ float    g_favg[B * 192];               // avg-branch sums (atomic acc)

// ---------------- helpers ----------------------------------------------------
__device__ __forceinline__ uint32_t smem_u32(const void* p) {
    uint32_t a;
    asm("{ .reg .u64 t; cvta.to.shared.u64 t, %1; cvt.u32.u64 %0, t; }" : "=r"(a) : "l"(p));
    return a;
}
__device__ __forceinline__ void cpa16(uint32_t dst, const void* src) {
    asm volatile("cp.async.cg.shared.global [%0], [%1], 16;" :: "r"(dst), "l"(src));
}
#define CP_COMMIT() asm volatile("cp.async.commit_group;" ::: "memory")
#define CP_WAIT0()  asm volatile("cp.async.wait_group 0;" ::: "memory")

__device__ __forceinline__ void ldsm4(uint32_t* r, uint32_t a) {
    asm volatile("ldmatrix.sync.aligned.m8n8.x4.shared.b16 {%0,%1,%2,%3}, [%4];"
                 : "=r"(r[0]), "=r"(r[1]), "=r"(r[2]), "=r"(r[3]) : "r"(a));
}
__device__ __forceinline__ void mma16816(float* d, const uint32_t* a, const uint32_t* b2) {
    asm volatile(
        "mma.sync.aligned.m16n8k16.row.col.f32.f16.f16.f32 "
        "{%0,%1,%2,%3},{%4,%5,%6,%7},{%8,%9},{%0,%1,%2,%3};"
        : "+f"(d[0]), "+f"(d[1]), "+f"(d[2]), "+f"(d[3])
        : "r"(a[0]), "r"(a[1]), "r"(a[2]), "r"(a[3]), "r"(b2[0]), "r"(b2[1]));
}
__device__ __forceinline__ uint32_t pack_h(float a, float b) {
    __half ha = __float2half_rn(a), hb = __float2half_rn(b);
    return (uint32_t)__half_as_ushort(ha) | ((uint32_t)__half_as_ushort(hb) << 16);
}
__device__ __forceinline__ uint32_t fenc(float f) {
    uint32_t u = __float_as_uint(f);
    return (u & 0x80000000u) ? ~u : (u | 0x80000000u);
}
__device__ __forceinline__ float fdec(uint32_t u) {
    return __uint_as_float((u & 0x80000000u) ? (u ^ 0x80000000u) : ~u);
}
// inline BN stats -> (scale, shift) for channel i (0..127)
__device__ __forceinline__ float2 bn_coef(int i, float gamma, float beta) {
    float n = (float)B * (float)TC;
    float mean = g_sum[i] / n;
    float var  = g_sumsq[i] / n - mean * mean;
    float sc = rsqrtf(var + 1e-5f) * gamma;
    return make_float2(sc, beta - mean * sc);
}

// ---------------------------------------------------------------------------
// Merged prep: grid (130, 32).
//   x < 129 : transpose x -> g_xh [b][t][ci] fp16 (float2 loads, unrolled)
//   x == 129: y < 21 -> W image for k=y; y == 21 -> init accumulators
__global__ void __launch_bounds__(256) k_prep(const float* __restrict__ x,
                                              const float* __restrict__ w1,
                                              const float* __restrict__ w2) {
    if (blockIdx.x == 129) {
        int k = blockIdx.y;
        if (k < KW) {
            uint32_t* dh = (uint32_t*)g_wh;
            for (int idx = threadIdx.x; idx < 128 * 32; idx += 256) {
                int n = idx >> 5, p = idx & 31, ci = 2 * p;
                const float* src = (n < 64) ? (w1 + ((size_t)n * C + ci) * KW + k)
                                            : (w2 + ((size_t)(n - 64) * C + ci) * KW + k);
                dh[(k * 128 + n) * 32 + p] = pack_h(src[0], src[KW]);
            }
        } else if (k == KW) {
            int i = threadIdx.x;
            if (i < 128) { g_sum[i] = 0.f; g_sumsq[i] = 0.f; }
            const uint32_t NEGINF = 0x007FFFFFu;   // fenc(-inf)
            for (int j = i; j < B * 64 * 4; j += 256) g_mm[j] = NEGINF;
            for (int j = i; j < B * 192; j += 256) g_favg[j] = 0.f;
        }
        return;
    }
    __shared__ float smx[64][129];
    const int b = blockIdx.y, t0 = blockIdx.x * 128;
    const int tid = threadIdx.x;
    // float2 loads: thread handles (ci, 2 consecutive t), fully unrolled
#pragma unroll
    for (int it = 0; it < 16; it++) {
        int idx = tid + it * 256;            // 0 .. 4095 over (ci, tf)
        int ci = idx >> 6, tf = idx & 63;
        int t = t0 + tf * 2;
        float2 v;
        if (t + 1 < T_IN) {
            v = *(const float2*)(x + ((size_t)b * C + ci) * T_IN + t);
        } else {
            v.x = (t < T_IN) ? x[((size_t)b * C + ci) * T_IN + t] : 0.f;
            v.y = 0.f;
        }
        smx[ci][2 * tf]     = v.x;
        smx[ci][2 * tf + 1] = v.y;
    }
    __syncthreads();
    uint32_t* dh = (uint32_t*)g_xh;
#pragma unroll
    for (int it = 0; it < 16; it++) {
        int idx = tid + it * 256;
        int tt = idx >> 5, p = idx & 31;
        size_t gi = ((size_t)b * TROWS + t0 + tt) * 32 + p;
        dh[gi] = pack_h(smx[2 * p][tt], smx[2 * p + 1][tt]);
    }
}

// ---------------------------------------------------------------------------
__device__ __forceinline__ void stage_w(uint32_t dst, int k, int tid) {
    const uint4* sh = g_wh + (size_t)k * 1024;
    for (int i = tid; i < 1024; i += 256) {
        int r = i >> 3, c2 = i & 7;
        cpa16(dst + r * 144 + c2 * 16, sh + i);
    }
}

// Main mma.sync conv: block (tile, b), 256 threads = 8 warps (2m x 4n),
// warp tile 64x32, D[t=128][n=128] in registers. 2 k per mainloop iteration.
// Epilogue: BN sums + fused exact max-pool bins (n<64), fp16 store (n>=64).
__global__ void __launch_bounds__(256, 2) k_conv(const int* __restrict__ orig_len) {
    extern __shared__ __align__(1024) char sm[];
    const int tile = blockIdx.x, b = blockIdx.y;
    const int t0 = tile * MT;
    const int tid = threadIdx.x;
    const int wid = tid >> 5, lane = tid & 31;
    const int wm = wid & 1, wn = wid >> 1;

    const uint32_t sm_u = smem_u32(sm);
    const uint32_t xs_h = sm_u;
    const uint32_t wb_u = sm_u + WB_OFF;

    // stage X tile (148 rows) + W[0], W[1] into pair-buffer 0
    {
        const uint4* sxh = g_xh + ((size_t)b * TROWS + t0) * 8;
        for (int i = tid; i < 1184; i += 256) {
            int r = i >> 3, c2 = i & 7;
            cpa16(xs_h + r * 144 + c2 * 16, sxh + i);
        }
        stage_w(wb_u, 0, tid);
        stage_w(wb_u + WSLOT, 1, tid);
        CP_COMMIT();
    }
    const int L = orig_len[b] - (KW - 1);
    const int strd = L >> 1, kern = (L + 1) >> 1;

    // per-warp ldmatrix base addresses
    uint32_t cA[4];
#pragma unroll
    for (int i = 0; i < 4; i++)
        cA[i] = (uint32_t)((wm * 64 + i * 16 + (lane & 15)) * 144 + ((lane >> 4) * 16));
    uint32_t cB[2];
#pragma unroll
    for (int p = 0; p < 2; p++)
        cB[p] = (uint32_t)((wn * 32 + p * 16 + ((lane >> 4) << 3) + (lane & 7)) * 144 +
                           (((lane >> 3) & 1) * 16));

    float acc[4][4][4];
#pragma unroll
    for (int i = 0; i < 4; i++)
#pragma unroll
        for (int j = 0; j < 4; j++)
#pragma unroll
            for (int e = 0; e < 4; e++) acc[i][j][e] = 0.f;

    CP_WAIT0();
    __syncthreads();

#pragma unroll 1
    for (int kk = 0; kk < KW; kk += 2) {
        const int buf = (kk >> 1) & 1;
        const uint32_t base = wb_u + buf * WPAIR;
        if (kk + 2 < KW) {
            const uint32_t nb = wb_u + (buf ^ 1) * WPAIR;
            stage_w(nb, kk + 2, tid);
            if (kk + 3 < KW) stage_w(nb + WSLOT, kk + 3, tid);
            CP_COMMIT();
        }
#pragma unroll 1
        for (int kq = 0; kq < 2; kq++) {
            const int k = kk + kq;
            if (k >= KW) break;
            const uint32_t axh = xs_h + k * 144;
            const uint32_t bwh = base + kq * WSLOT;
#pragma unroll
            for (int ks = 0; ks < 4; ks++) {
                uint32_t ah[4][4], bh[2][4];
#pragma unroll
                for (int i = 0; i < 4; i++) ldsm4(ah[i], axh + cA[i] + ks * 32);
#pragma unroll
                for (int p = 0; p < 2; p++) ldsm4(bh[p], bwh + cB[p] + ks * 32);
#pragma unroll
                for (int i = 0; i < 4; i++)
#pragma unroll
                    for (int j = 0; j < 4; j++)
                        mma16816(acc[i][j], ah[i], &bh[j >> 1][(j & 1) * 2]);
            }
        }
        CP_WAIT0();
        __syncthreads();
    }

    // Epilogue: acc -> smem [t][n] (stride 136 floats; aliases X+W regions)
    float* ep = (float*)sm;
#pragma unroll
    for (int i = 0; i < 4; i++) {
        int tl = wm * 64 + i * 16 + (lane >> 2);
#pragma unroll
        for (int j = 0; j < 4; j++) {
            int nn = wn * 32 + j * 8 + (lane & 3) * 2;
            *(float2*)&ep[tl * 136 + nn]       = make_float2(acc[i][j][0], acc[i][j][1]);
            *(float2*)&ep[(tl + 8) * 136 + nn] = make_float2(acc[i][j][2], acc[i][j][3]);
        }
    }
    __syncthreads();
    // BN + max-pool scan: 2-way t-split, all 8 warps
    {
        float* red = (float*)(sm + RED_OFF);
        const int n = tid & 127, half = tid >> 7;
        float s = 0.f, q = 0.f;
        float m0 = -INFINITY, m1 = -INFINITY, n0 = -INFINITY, n1 = -INFINITY;
        const int tbeg = half * 64, tend = tbeg + 64;
        for (int t = tbeg; t < tend; t++) {
            int tt = t0 + t;
            if (tt < TC) {
                float v = ep[t * 136 + n];
                s += v; q = fmaf(v, v, q);
                if (n < 64) {
                    if (tt < kern)            { m0 = fmaxf(m0, v); n0 = fmaxf(n0, -v); }
                    if (tt >= strd && tt < L) { m1 = fmaxf(m1, v); n1 = fmaxf(n1, -v); }
                }
            }
        }
        red[tid]        = s;  red[256 + tid]  = q;
        red[512 + tid]  = m0; red[768 + tid]  = n0;
        red[1024 + tid] = m1; red[1280 + tid] = n1;
        __syncthreads();
        if (tid < 128) {
            atomicAdd(&g_sum[tid],   red[tid] + red[tid + 128]);
            atomicAdd(&g_sumsq[tid], red[256 + tid] + red[384 + tid]);
            if (tid < 64) {
                unsigned* mm = g_mm + (b * 64 + tid) * 4;
                atomicMax(&mm[0], fenc(fmaxf(red[512 + tid],  red[640 + tid])));
                atomicMax(&mm[1], fenc(fmaxf(red[768 + tid],  red[896 + tid])));
                atomicMax(&mm[2], fenc(fmaxf(red[1024 + tid], red[1152 + tid])));
                atomicMax(&mm[3], fenc(fmaxf(red[1280 + tid], red[1408 + tid])));
            }
        }
    }
    // store avg-branch y (n in [64,128)) as fp16 [b][t][c]
    __half* ybase = g_y2 + ((size_t)b * 16384 + t0) * 64;
    for (int i = tid; i < 2048; i += 256) {
        int t = i >> 4, p4 = i & 15;
        float4 v = *(float4*)&ep[t * 136 + 64 + p4 * 4];
        __half2 h0 = __floats2half2_rn(v.x, v.y);
        __half2 h1 = __floats2half2_rn(v.z, v.w);
        uint2 u;
        u.x = *(uint32_t*)&h0;
        u.y = *(uint32_t*)&h1;
        *(uint2*)(ybase + (size_t)t * 64 + p4 * 4) = u;
    }
}

// ---------------------------------------------------------------------------
// Avg-branch SPP partial pass over fp16 y2 [b][t][c(64)]. TSPLIT blocks per b;
// partials combined via atomicAdd into g_favg.
__global__ void __launch_bounds__(256) k_spp(const int* __restrict__ orig_len,
                                             const float* __restrict__ g2,
                                             const float* __restrict__ b2) {
    const int s = blockIdx.x, b = blockIdx.y;
    const int L = orig_len[b] - (KW - 1);
    const int strd = L >> 1, kern = (L + 1) >> 1;
    const int chunk = (L + TSPLIT - 1) / TSPLIT;
    const int tb = s * chunk;
    const int te = min(L, tb + chunk);
    const int p = threadIdx.x & 31, h = threadIdx.x >> 5;
    const int c0 = 2 * p, c1 = 2 * p + 1;
    float2 k0 = bn_coef(64 + c0, g2[c0], b2[c0]);
    float2 k1 = bn_coef(64 + c1, g2[c1], b2[c1]);
    const __half2* __restrict__ base =
        (const __half2*)g_y2 + (size_t)b * 16384 * 32 + p;

    float2 sa = make_float2(0.f, 0.f), s0 = sa, s1 = sa;
#pragma unroll 8
    for (int t = tb + h; t < te; t += 8) {
        float2 v = __half22float2(base[(size_t)t * 32]);
        v.x = fmaf(v.x, k0.x, k0.y); v.y = fmaf(v.y, k1.x, k1.y);
        v.x = (v.x > 0.f) ? v.x : 0.01f * v.x;
        v.y = (v.y > 0.f) ? v.y : 0.01f * v.y;
        sa.x += v.x; sa.y += v.y;
        if (t < kern) { s0.x += v.x; s0.y += v.y; }
        if (t >= strd) { s1.x += v.x; s1.y += v.y; }
    }
    __shared__ float2 r0[256], r1[256], r2[256];
    r0[threadIdx.x] = sa; r1[threadIdx.x] = s0; r2[threadIdx.x] = s1;
    __syncthreads();
    if (h == 0) {
#pragma unroll
        for (int g = 1; g < 8; g++) {
            int o = threadIdx.x + g * 32;
            sa.x += r0[o].x; sa.y += r0[o].y;
            s0.x += r1[o].x; s0.y += r1[o].y;
            s1.x += r2[o].x; s1.y += r2[o].y;
        }
        float* pp = g_favg + b * 192;
        atomicAdd(&pp[c0], sa.x);        atomicAdd(&pp[c1], sa.y);
        atomicAdd(&pp[64 + c0], s0.x);   atomicAdd(&pp[64 + c1], s0.y);
        atomicAdd(&pp[128 + c0], s1.x);  atomicAdd(&pp[128 + c1], s1.y);
    }
}

// Finalize: max-branch from g_mm, avg-branch from g_favg -> feat -> FC.
__global__ void k_spp2fc(const int* __restrict__ orig_len,
                         const float* __restrict__ g1, const float* __restrict__ b1,
                         const float* __restrict__ fc_w,
                         const float* __restrict__ fc_b,
                         float* __restrict__ out) {
    int b = blockIdx.x, n = threadIdx.x;
    __shared__ float feat[384];
    int L = orig_len[b] - (KW - 1);
    int kern = (L + 1) >> 1;
    if (n < 128) {
        if (n < 64) {
            float2 kk = bn_coef(n, g1[n], b1[n]);
            const unsigned* mm = g_mm + (b * 64 + n) * 4;
            float M0 = fdec(mm[0]), N0 = -fdec(mm[1]);
            float M1 = fdec(mm[2]), N1 = -fdec(mm[3]);
            float v0 = (kk.x >= 0.f) ? fmaf(kk.x, M0, kk.y) : fmaf(kk.x, N0, kk.y);
            float v1 = (kk.x >= 0.f) ? fmaf(kk.x, M1, kk.y) : fmaf(kk.x, N1, kk.y);
            v0 = (v0 > 0.f) ? v0 : 0.01f * v0;
            v1 = (v1 > 0.f) ? v1 : 0.01f * v1;
            feat[n] = fmaxf(v0, v1);
            feat[64 + 2 * n] = v0;
            feat[65 + 2 * n] = v1;
        } else {
            int c = n - 64;
            const float* pp = g_favg + b * 192;
            feat[192 + c] = pp[c] / (float)L;
            feat[256 + 2 * c] = pp[64 + c] / (float)kern;
            feat[257 + 2 * c] = pp[128 + c] / (float)kern;
        }
    }
    __syncthreads();
    if (n < 64) {
        int task = n >> 5, lane = n & 31;
        float acc = 0.f;
        for (int j = lane; j < 384; j += 32)
            acc = fmaf(feat[j], fc_w[task * 384 + j], acc);
#pragma unroll
        for (int off = 16; off; off >>= 1)
            acc += __shfl_down_sync(0xffffffffu, acc, off);
        if (lane == 0) out[b * 2 + task] = acc + fc_b[task];
    }
}

// ---------------------------------------------------------------------------
extern "C" void kernel_launch(void* const* d_in, const int* in_sizes, int n_in,
                              void* d_out, int out_size) {
    const float* x        = (const float*)d_in[0];
    const int*   orig_len = (const int*)  d_in[1];
    const float* w1       = (const float*)d_in[2];
    const float* g1       = (const float*)d_in[3];
    const float* b1       = (const float*)d_in[4];
    const float* w2       = (const float*)d_in[5];
    const float* g2       = (const float*)d_in[6];
    const float* b2       = (const float*)d_in[7];
    const float* fcw      = (const float*)d_in[8];
    const float* fcb      = (const float*)d_in[9];
    float* out = (float*)d_out;

    cudaFuncSetAttribute(k_conv, cudaFuncAttributeMaxDynamicSharedMemorySize,
                         SMEM_TOTAL);

    dim3 gp(130, 32);
    k_prep<<<gp, 256>>>(x, w1, w2);
    dim3 gc(NTILES, B);
    k_conv<<<gc, 256, SMEM_TOTAL>>>(orig_len);
    dim3 gs(TSPLIT, B);
    k_spp<<<gs, 256>>>(orig_len, g2, b2);
    k_spp2fc<<<B, 128>>>(orig_len, g1, b1, fcw, fcb, out);
}